// round 15
// baseline (speedup 1.0000x reference)
#include <cuda_runtime.h>
#include <cuda_bf16.h>
#include <stdint.h>
#include <math.h>
#include <float.h>

// Problem constants (shapes fixed by the dataset generator)
#define NNODES 50000
#define FIN    128
#define DDIM   250
#define DPAD   256
#define HDIM   256
#define EMAXT  850000   // E + N self loops

// ---------------- scratch (device globals; no runtime allocation) ----------
__device__ __align__(16) float g_xl [NNODES * DPAD];
__device__ __align__(16) float g_xr [NNODES * DPAD];
__device__ int   g_deg   [NNODES];
__device__ int   g_cursor[NNODES];
__device__ int   g_rowptr[NNODES + 1];
__device__ int   g_colsrc[EMAXT];
// split-bf16 buffers (6 weight pairs: l1{l,r}, l2{l,r}, head{a,b})
__device__ __align__(16) __nv_bfloat16 g_ahi[NNODES * DPAD];
__device__ __align__(16) __nv_bfloat16 g_alo[NNODES * DPAD];
__device__ __align__(16) __nv_bfloat16 g_bthi[6][256 * 256];
__device__ __align__(16) __nv_bfloat16 g_btlo[6][256 * 256];

// ---------------- CSR build ------------------------------------------------
__global__ void zero_deg_kernel(int* deg, int n) {
    int i = blockIdx.x * blockDim.x + threadIdx.x;
    if (i < n) deg[i] = 0;
}

__global__ void hist_kernel(const int* __restrict__ ei, int* __restrict__ deg,
                            int E, int Etot) {
    int k = blockIdx.x * blockDim.x + threadIdx.x;
    if (k >= Etot) return;
    int dst = (k < E) ? ei[E + k] : (k - E);
    atomicAdd(&deg[dst], 1);
}

__global__ void scan_kernel(const int* __restrict__ deg,
                            int* __restrict__ rowptr,
                            int* __restrict__ cursor, int n) {
    __shared__ int wpre[32];
    __shared__ int carry;
    int lane = threadIdx.x & 31, wid = threadIdx.x >> 5;
    if (threadIdx.x == 0) { carry = 0; rowptr[0] = 0; }
    __syncthreads();
    for (int base = 0; base < n; base += 1024) {
        int i = base + threadIdx.x;
        int v = (i < n) ? deg[i] : 0;
        int x = v;
        #pragma unroll
        for (int off = 1; off < 32; off <<= 1) {
            int t = __shfl_up_sync(0xffffffffu, x, off);
            if (lane >= off) x += t;
        }
        if (lane == 31) wpre[wid] = x;
        __syncthreads();
        if (wid == 0) {
            int y = wpre[lane];
            #pragma unroll
            for (int off = 1; off < 32; off <<= 1) {
                int t = __shfl_up_sync(0xffffffffu, y, off);
                if (lane >= off) y += t;
            }
            wpre[lane] = y;
        }
        __syncthreads();
        int warpoff = (wid == 0) ? 0 : wpre[wid - 1];
        int incl = x + warpoff + carry;
        if (i < n) { rowptr[i + 1] = incl; cursor[i] = incl - v; }
        __syncthreads();
        if (threadIdx.x == 1023) carry = incl;
        __syncthreads();
    }
}

__global__ void scatter_kernel(const int* __restrict__ ei,
                               int* __restrict__ cursor,
                               int* __restrict__ colsrc, int E, int Etot) {
    int k = blockIdx.x * blockDim.x + threadIdx.x;
    if (k >= Etot) return;
    int src, dst;
    if (k < E) { src = ei[k]; dst = ei[E + k]; }
    else       { src = k - E; dst = k - E; }
    int pos = atomicAdd(&cursor[dst], 1);
    colsrc[pos] = src;
}

// ---------------- split-bf16 conversions -----------------------------------
// conv_act only used for x: Kreal == Kpad == 128 (shift 7), no padding branch
__global__ void conv_act_kernel(const float* __restrict__ A, int M,
                                __nv_bfloat16* __restrict__ hi,
                                __nv_bfloat16* __restrict__ lo) {
    int idx = blockIdx.x * blockDim.x + threadIdx.x;
    int total = M << 7;
    int stride = gridDim.x * blockDim.x;
    for (; idx < total; idx += stride) {
        float v = A[idx];
        __nv_bfloat16 h = __float2bfloat16(v);
        float r = v - __bfloat162float(h);
        hi[idx] = h;
        lo[idx] = __float2bfloat16(r);
    }
}

__global__ void conv_wt_kernel(const float* __restrict__ W, int ldw,
                               int Kreal, int Nreal, int Kpad,
                               __nv_bfloat16* __restrict__ hi,
                               __nv_bfloat16* __restrict__ lo) {
    int idx = blockIdx.x * blockDim.x + threadIdx.x;
    int total = 256 * Kpad;
    if (idx >= total) return;
    int n = idx / Kpad, k = idx - n * Kpad;
    float v = (n < Nreal && k < Kreal) ? W[(size_t)k * ldw + n] : 0.f;
    __nv_bfloat16 h = __float2bfloat16(v);
    float r = v - __bfloat162float(h);
    hi[idx] = h;
    lo[idx] = __float2bfloat16(r);
}

// ---------------- mma / ldmatrix / cp.async helpers ------------------------
__device__ __forceinline__ void mma16816(float* c, const unsigned* a,
                                         unsigned b0, unsigned b1) {
    asm volatile(
        "mma.sync.aligned.m16n8k16.row.col.f32.bf16.bf16.f32 "
        "{%0,%1,%2,%3},{%4,%5,%6,%7},{%8,%9},{%0,%1,%2,%3};"
        : "+f"(c[0]), "+f"(c[1]), "+f"(c[2]), "+f"(c[3])
        : "r"(a[0]), "r"(a[1]), "r"(a[2]), "r"(a[3]), "r"(b0), "r"(b1));
}

__device__ __forceinline__ void ldsm_x4(unsigned* r, unsigned addr) {
    asm volatile("ldmatrix.sync.aligned.m8n8.x4.shared.b16 {%0,%1,%2,%3}, [%4];"
                 : "=r"(r[0]), "=r"(r[1]), "=r"(r[2]), "=r"(r[3]) : "r"(addr));
}

__device__ __forceinline__ void cpasync16(unsigned saddr, const void* gaddr, int bytes) {
    asm volatile("cp.async.cg.shared.global [%0], [%1], 16, %2;"
                 :: "r"(saddr), "l"(gaddr), "r"(bytes));
}

// ---------------- fused dual-B split-bf16 tensor-core GEMM -----------------
// (round-13 proven config: 256 thr, 128x128 tile, 2-stage, 2 blocks/SM)
#define SROW 40                       // bf16 per smem row (32 k + 8 pad)
#define ARR_BYTES (128 * SROW * 2)    // 10240
#define STAGE_BYTES (4 * ARR_BYTES)   // 40960  (Ah, Al, Bh, Bl)
#define GEMM_SMEM (2 * STAGE_BYTES)   // 81920

extern __shared__ __align__(16) unsigned char g_dynsmem[];

__global__ void __launch_bounds__(256, 2)
gemm_mma_dual_kernel(const __nv_bfloat16* __restrict__ Ahi,
                     const __nv_bfloat16* __restrict__ Alo, int Kpad,
                     const __nv_bfloat16* __restrict__ BT1h,
                     const __nv_bfloat16* __restrict__ BT1l,
                     const __nv_bfloat16* __restrict__ BT2h,
                     const __nv_bfloat16* __restrict__ BT2l,
                     const float* __restrict__ bias1,
                     const float* __restrict__ bias2,
                     float* __restrict__ C1, float* __restrict__ C2,
                     int ldc, int M, int Nreal) {
    unsigned smem_u32 = (unsigned)__cvta_generic_to_shared(g_dynsmem);
    int tid = threadIdx.x;
    int lane = tid & 31, wid = tid >> 5;
    int g = lane >> 2, tk = lane & 3;
    int wm = (wid & 3) * 32;       // warp row offset in tile
    int wn = (wid >> 2) * 64;      // warp col offset in tile
    int row0 = blockIdx.y * 128;
    int half = blockIdx.x >> 1;
    int col0 = (blockIdx.x & 1) * 128;

    const __nv_bfloat16* BTh = half ? BT2h : BT1h;
    const __nv_bfloat16* BTl = half ? BT2l : BT1l;
    const float* bias = half ? bias2 : bias1;
    float* C = half ? C2 : C1;

    float acc[2][8][4];
    #pragma unroll
    for (int i = 0; i < 2; i++)
        #pragma unroll
        for (int j = 0; j < 8; j++)
            #pragma unroll
            for (int q = 0; q < 4; q++) acc[i][j][q] = 0.f;

    int nk = Kpad >> 5;

    auto stage_tiles = [&](int buf, int k0) {
        unsigned sb = smem_u32 + buf * STAGE_BYTES;
        #pragma unroll
        for (int it = 0; it < 2; it++) {
            int f = tid + it * 256;
            int r = f >> 2, kg = f & 3;
            unsigned soff = (unsigned)(r * SROW + kg * 8) * 2;
            int arow = row0 + r;
            int ab = (arow < M) ? 16 : 0;
            int arc = (arow < M) ? arow : 0;
            size_t ka = (size_t)arc * Kpad + k0 + kg * 8;
            cpasync16(sb + soff,                 Ahi + ka, ab);
            cpasync16(sb + ARR_BYTES + soff,     Alo + ka, ab);
            size_t kb = (size_t)(col0 + r) * Kpad + k0 + kg * 8;
            cpasync16(sb + 2 * ARR_BYTES + soff, BTh + kb, 16);
            cpasync16(sb + 3 * ARR_BYTES + soff, BTl + kb, 16);
        }
    };

    stage_tiles(0, 0);
    asm volatile("cp.async.commit_group;");

    for (int i = 0; i < nk; i++) {
        if (i + 1 < nk) {
            stage_tiles((i + 1) & 1, (i + 1) * 32);
            asm volatile("cp.async.commit_group;");
            asm volatile("cp.async.wait_group 1;");
        } else {
            asm volatile("cp.async.wait_group 0;");
        }
        __syncthreads();

        unsigned sb = smem_u32 + (i & 1) * STAGE_BYTES;
        #pragma unroll
        for (int kk = 0; kk < 32; kk += 16) {
            unsigned ah[2][4], al[2][4];
            #pragma unroll
            for (int mf = 0; mf < 2; mf++) {
                int arow = wm + mf * 16 + (lane & 15);
                int acol = kk + ((lane >> 4) << 3);
                unsigned addr = sb + (unsigned)(arow * SROW + acol) * 2;
                ldsm_x4(ah[mf], addr);
                ldsm_x4(al[mf], addr + ARR_BYTES);
            }
            #pragma unroll
            for (int pr = 0; pr < 4; pr++) {
                unsigned bh[4], bl[4];
                int brow = wn + pr * 16 + (lane & 7) + ((lane >> 4) << 3);
                int bcol = kk + (((lane >> 3) & 1) << 3);
                unsigned addr = sb + 2 * ARR_BYTES + (unsigned)(brow * SROW + bcol) * 2;
                ldsm_x4(bh, addr);
                ldsm_x4(bl, addr + ARR_BYTES);
                #pragma unroll
                for (int sub = 0; sub < 2; sub++) {
                    int nf = pr * 2 + sub;
                    unsigned b0h = bh[sub * 2], b1h = bh[sub * 2 + 1];
                    unsigned b0l = bl[sub * 2], b1l = bl[sub * 2 + 1];
                    #pragma unroll
                    for (int mf = 0; mf < 2; mf++) {
                        mma16816(acc[mf][nf], ah[mf], b0h, b1h);  // hi*hi
                        mma16816(acc[mf][nf], al[mf], b0h, b1h);  // lo*hi
                        mma16816(acc[mf][nf], ah[mf], b0l, b1l);  // hi*lo
                    }
                }
            }
        }
        __syncthreads();
    }

    // epilogue
    #pragma unroll
    for (int mf = 0; mf < 2; mf++) {
        #pragma unroll
        for (int nf = 0; nf < 8; nf++) {
            int col = col0 + wn + nf * 8 + 2 * tk;
            if (col >= Nreal) continue;          // cols even, Nreal even -> col+1 valid
            float bv0 = bias ? bias[col]     : 0.f;
            float bv1 = bias ? bias[col + 1] : 0.f;
            int r = row0 + wm + mf * 16 + g;
            if (r < M) {
                float2 v = make_float2(acc[mf][nf][0] + bv0, acc[mf][nf][1] + bv1);
                *(float2*)&C[(size_t)r * ldc + col] = v;
            }
            int r2 = r + 8;
            if (r2 < M) {
                float2 v = make_float2(acc[mf][nf][2] + bv0, acc[mf][nf][3] + bv1);
                *(float2*)&C[(size_t)r2 * ldc + col] = v;
            }
        }
    }
}

// ---------------- fused GATv2 softmax-aggregate (writes split-bf16) --------
__global__ void gat_agg_kernel(const float* __restrict__ xl,
                               const float* __restrict__ xr,
                               const float* __restrict__ att,
                               const int* __restrict__ rowptr,
                               const int* __restrict__ colsrc,
                               __nv_bfloat16* __restrict__ ohi,
                               __nv_bfloat16* __restrict__ olo,
                               int n, int do_relu) {
    int w = (blockIdx.x * blockDim.x + threadIdx.x) >> 5;
    if (w >= n) return;
    int lane = threadIdx.x & 31;

    float attv[8], xrv[8], acc[8];
    #pragma unroll
    for (int j = 0; j < 8; j++) {
        int d = j * 32 + lane;
        bool ok = d < DDIM;
        attv[j] = ok ? att[d] : 0.f;
        xrv[j]  = ok ? xr[(size_t)w * DPAD + d] : 0.f;
        acc[j] = 0.f;
    }
    float m = -FLT_MAX, s = 0.f;
    int beg = rowptr[w], end = rowptr[w + 1];
    for (int p = beg; p < end; p++) {
        int src = colsrc[p];
        const float* xs = xl + (size_t)src * DPAD;
        float xv[8];
        float part = 0.f;
        #pragma unroll
        for (int j = 0; j < 8; j++) {
            int d = j * 32 + lane;
            float v = (d < DDIM) ? xs[d] : 0.f;
            xv[j] = v;
            float hsum = v + xrv[j];
            float lr = hsum > 0.f ? hsum : 0.2f * hsum;
            part += attv[j] * lr;
        }
        #pragma unroll
        for (int off = 16; off; off >>= 1)
            part += __shfl_xor_sync(0xffffffffu, part, off);
        float mn = fmaxf(m, part);
        float c   = __expf(m - mn);
        float wgt = __expf(part - mn);
        s = s * c + wgt;
        #pragma unroll
        for (int j = 0; j < 8; j++) acc[j] = acc[j] * c + wgt * xv[j];
        m = mn;
    }
    float inv = 1.f / s;
    #pragma unroll
    for (int j = 0; j < 8; j++) {
        int d = j * 32 + lane;
        float v = acc[j] * inv;
        if (do_relu) v = fmaxf(v, 0.f);
        if (d >= DDIM) v = 0.f;
        __nv_bfloat16 hb = __float2bfloat16(v);
        float r = v - __bfloat162float(hb);
        size_t o = (size_t)w * DPAD + d;
        ohi[o] = hb;
        olo[o] = __float2bfloat16(r);
    }
}

// ---------------- head: out[q] = relu(dot(relu(A[q0]+B[q1]), Wm2)+bm2) -----
__global__ void head_kernel(const int* __restrict__ query,
                            const float* __restrict__ Atab,
                            const float* __restrict__ Btab,
                            const float* __restrict__ Wm2,
                            const float* __restrict__ bm2,
                            float* __restrict__ out, int Q) {
    int q = (blockIdx.x * blockDim.x + threadIdx.x) >> 5;
    if (q >= Q) return;
    int lane = threadIdx.x & 31;
    int q0 = query[2 * q], q1 = query[2 * q + 1];
    const float* a = Atab + (size_t)q0 * HDIM;
    const float* b = Btab + (size_t)q1 * HDIM;
    float partial = 0.f;
    #pragma unroll
    for (int j = lane; j < HDIM; j += 32) {
        float h = fmaxf(a[j] + b[j], 0.f);
        partial += h * Wm2[j];
    }
    #pragma unroll
    for (int off = 16; off; off >>= 1)
        partial += __shfl_down_sync(0xffffffffu, partial, off);
    if (lane == 0) out[q] = fmaxf(partial + bm2[0], 0.f);
}

// ---------------------------------------------------------------------------
extern "C" void kernel_launch(void* const* d_in, const int* in_sizes, int n_in,
                              void* d_out, int out_size) {
    const float* x    = (const float*)d_in[0];
    const int*   ei   = (const int*)  d_in[1];
    const int*   qry  = (const int*)  d_in[2];
    const float* W1l  = (const float*)d_in[3];
    const float* b1l  = (const float*)d_in[4];
    const float* W1r  = (const float*)d_in[5];
    const float* b1r  = (const float*)d_in[6];
    const float* att1 = (const float*)d_in[7];
    const float* W2l  = (const float*)d_in[8];
    const float* b2l  = (const float*)d_in[9];
    const float* W2r  = (const float*)d_in[10];
    const float* b2r  = (const float*)d_in[11];
    const float* att2 = (const float*)d_in[12];
    const float* Wm1  = (const float*)d_in[13];
    const float* bm1  = (const float*)d_in[14];
    const float* Wm2  = (const float*)d_in[15];
    const float* bm2  = (const float*)d_in[16];
    float* out = (float*)d_out;

    const int N = in_sizes[0] / FIN;        // 50000
    const int E = in_sizes[1] / 2;          // 800000
    const int Q = in_sizes[2] / 2;          // 200000
    const int Etot = E + N;

    float *p_xl, *p_xr;
    int *p_deg, *p_cursor, *p_rowptr, *p_colsrc;
    __nv_bfloat16 *p_ahi, *p_alo, *p_bthi, *p_btlo;
    cudaGetSymbolAddress((void**)&p_xl,     g_xl);
    cudaGetSymbolAddress((void**)&p_xr,     g_xr);
    cudaGetSymbolAddress((void**)&p_deg,    g_deg);
    cudaGetSymbolAddress((void**)&p_cursor, g_cursor);
    cudaGetSymbolAddress((void**)&p_rowptr, g_rowptr);
    cudaGetSymbolAddress((void**)&p_colsrc, g_colsrc);
    cudaGetSymbolAddress((void**)&p_ahi,    g_ahi);
    cudaGetSymbolAddress((void**)&p_alo,    g_alo);
    cudaGetSymbolAddress((void**)&p_bthi,   g_bthi);
    cudaGetSymbolAddress((void**)&p_btlo,   g_btlo);
    __nv_bfloat16* bthi[6], *btlo[6];
    for (int i = 0; i < 6; i++) {
        bthi[i] = p_bthi + i * 256 * 256;
        btlo[i] = p_btlo + i * 256 * 256;
    }

    cudaFuncSetAttribute(gemm_mma_dual_kernel,
                         cudaFuncAttributeMaxDynamicSharedMemorySize, GEMM_SMEM);

    const int TPB = 256;
    int agg_blocks = (N * 32 + TPB - 1) / TPB;
    int wt_blocks = (256 * 256 + TPB - 1) / TPB;
    dim3 ggrid(4, (N + 127) / 128);   // 2 col-tiles x 2 weight halves

    // ---- fork a non-blocking side stream for independent work -------------
    cudaStream_t s2;
    cudaStreamCreateWithFlags(&s2, cudaStreamNonBlocking);
    cudaEvent_t ev0, evw, ev1;
    cudaEventCreateWithFlags(&ev0, cudaEventDisableTiming);
    cudaEventCreateWithFlags(&evw, cudaEventDisableTiming);
    cudaEventCreateWithFlags(&ev1, cudaEventDisableTiming);
    cudaEventRecord(ev0, 0);

    // ---------- side: ALL weight conversions + CSR build -------------------
    cudaStreamWaitEvent(s2, ev0, 0);
    conv_wt_kernel<<<wt_blocks, TPB, 0, s2>>>(W1l, DDIM, FIN, DDIM, FIN, bthi[0], btlo[0]);
    conv_wt_kernel<<<wt_blocks, TPB, 0, s2>>>(W1r, DDIM, FIN, DDIM, FIN, bthi[1], btlo[1]);
    cudaEventRecord(evw, s2);   // layer-1 weights ready
    zero_deg_kernel<<<(N + TPB - 1) / TPB, TPB, 0, s2>>>(p_deg, N);
    hist_kernel<<<(Etot + TPB - 1) / TPB, TPB, 0, s2>>>(ei, p_deg, E, Etot);
    scan_kernel<<<1, 1024, 0, s2>>>(p_deg, p_rowptr, p_cursor, N);
    scatter_kernel<<<(Etot + TPB - 1) / TPB, TPB, 0, s2>>>(ei, p_cursor, p_colsrc, E, Etot);
    conv_wt_kernel<<<wt_blocks, TPB, 0, s2>>>(W2l, DDIM, DDIM, DDIM, DPAD, bthi[2], btlo[2]);
    conv_wt_kernel<<<wt_blocks, TPB, 0, s2>>>(W2r, DDIM, DDIM, DDIM, DPAD, bthi[3], btlo[3]);
    conv_wt_kernel<<<wt_blocks, TPB, 0, s2>>>(Wm1,               HDIM, DDIM, HDIM, DPAD, bthi[4], btlo[4]);
    conv_wt_kernel<<<wt_blocks, TPB, 0, s2>>>(Wm1 + DDIM * HDIM, HDIM, DDIM, HDIM, DPAD, bthi[5], btlo[5]);
    cudaEventRecord(ev1, s2);

    // ---------- main: conv_act(x) overlaps side; gemm1 after evw -----------
    conv_act_kernel<<<2048, TPB>>>(x, N, p_ahi, p_alo);
    cudaStreamWaitEvent(0, evw, 0);
    gemm_mma_dual_kernel<<<ggrid, 256, GEMM_SMEM>>>(p_ahi, p_alo, FIN,
        bthi[0], btlo[0], bthi[1], btlo[1], b1l, b1r, p_xl, p_xr, DPAD, N, DDIM);

    // ---------- join, then the dependent chain -----------------------------
    cudaStreamWaitEvent(0, ev1, 0);

    gat_agg_kernel<<<agg_blocks, TPB>>>(p_xl, p_xr, att1, p_rowptr, p_colsrc,
                                        p_ahi, p_alo, N, 1);

    gemm_mma_dual_kernel<<<ggrid, 256, GEMM_SMEM>>>(p_ahi, p_alo, DPAD,
        bthi[2], btlo[2], bthi[3], btlo[3], b2l, b2r, p_xl, p_xr, DPAD, N, DDIM);

    gat_agg_kernel<<<agg_blocks, TPB>>>(p_xl, p_xr, att2, p_rowptr, p_colsrc,
                                        p_ahi, p_alo, N, 0);

    gemm_mma_dual_kernel<<<ggrid, 256, GEMM_SMEM>>>(p_ahi, p_alo, DPAD,
        bthi[4], btlo[4], bthi[5], btlo[5], bm1, nullptr, p_xl, p_xr, HDIM, N, HDIM);

    int q_blocks = (Q * 32 + TPB - 1) / TPB;
    head_kernel<<<q_blocks, TPB>>>(qry, p_xl, p_xr, Wm2, bm2, out, Q);

    cudaEventDestroy(ev0);
    cudaEventDestroy(evw);
    cudaEventDestroy(ev1);
    cudaStreamDestroy(s2);
}

// round 16
// speedup vs baseline: 1.0736x; 1.0736x over previous
#include <cuda_runtime.h>
#include <cuda_bf16.h>
#include <stdint.h>
#include <math.h>
#include <float.h>

// Problem constants (shapes fixed by the dataset generator)
#define NNODES 50000
#define FIN    128
#define DDIM   250
#define DPAD   256
#define HDIM   256
#define EMAXT  850000   // E + N self loops

// ---------------- scratch (device globals; no runtime allocation) ----------
__device__ __align__(16) float g_xl [NNODES * DPAD];
__device__ __align__(16) float g_xr [NNODES * DPAD];
__device__ int   g_deg   [NNODES];
__device__ int   g_cursor[NNODES];
__device__ int   g_rowptr[NNODES + 1];
__device__ int   g_colsrc[EMAXT];
// split-bf16 buffers (6 weight pairs: l1{l,r}, l2{l,r}, head{a,b})
__device__ __align__(16) __nv_bfloat16 g_ahi[NNODES * DPAD];
__device__ __align__(16) __nv_bfloat16 g_alo[NNODES * DPAD];
__device__ __align__(16) __nv_bfloat16 g_bthi[6][256 * 256];
__device__ __align__(16) __nv_bfloat16 g_btlo[6][256 * 256];

// ---------------- CSR build ------------------------------------------------
__global__ void zero_deg_kernel(int* deg, int n) {
    int i = blockIdx.x * blockDim.x + threadIdx.x;
    if (i < n) deg[i] = 0;
}

__global__ void hist_kernel(const int* __restrict__ ei, int* __restrict__ deg,
                            int E, int Etot) {
    int k = blockIdx.x * blockDim.x + threadIdx.x;
    if (k >= Etot) return;
    int dst = (k < E) ? ei[E + k] : (k - E);
    atomicAdd(&deg[dst], 1);
}

__global__ void scan_kernel(const int* __restrict__ deg,
                            int* __restrict__ rowptr,
                            int* __restrict__ cursor, int n) {
    __shared__ int wpre[32];
    __shared__ int carry;
    int lane = threadIdx.x & 31, wid = threadIdx.x >> 5;
    if (threadIdx.x == 0) { carry = 0; rowptr[0] = 0; }
    __syncthreads();
    for (int base = 0; base < n; base += 1024) {
        int i = base + threadIdx.x;
        int v = (i < n) ? deg[i] : 0;
        int x = v;
        #pragma unroll
        for (int off = 1; off < 32; off <<= 1) {
            int t = __shfl_up_sync(0xffffffffu, x, off);
            if (lane >= off) x += t;
        }
        if (lane == 31) wpre[wid] = x;
        __syncthreads();
        if (wid == 0) {
            int y = wpre[lane];
            #pragma unroll
            for (int off = 1; off < 32; off <<= 1) {
                int t = __shfl_up_sync(0xffffffffu, y, off);
                if (lane >= off) y += t;
            }
            wpre[lane] = y;
        }
        __syncthreads();
        int warpoff = (wid == 0) ? 0 : wpre[wid - 1];
        int incl = x + warpoff + carry;
        if (i < n) { rowptr[i + 1] = incl; cursor[i] = incl - v; }
        __syncthreads();
        if (threadIdx.x == 1023) carry = incl;
        __syncthreads();
    }
}

__global__ void scatter_kernel(const int* __restrict__ ei,
                               int* __restrict__ cursor,
                               int* __restrict__ colsrc, int E, int Etot) {
    int k = blockIdx.x * blockDim.x + threadIdx.x;
    if (k >= Etot) return;
    int src, dst;
    if (k < E) { src = ei[k]; dst = ei[E + k]; }
    else       { src = k - E; dst = k - E; }
    int pos = atomicAdd(&cursor[dst], 1);
    colsrc[pos] = src;
}

// ---------------- split-bf16 conversions -----------------------------------
// conv_act only used for x: Kreal == Kpad == 128, no padding branch
__global__ void conv_act_kernel(const float* __restrict__ A, int M,
                                __nv_bfloat16* __restrict__ hi,
                                __nv_bfloat16* __restrict__ lo) {
    int idx = blockIdx.x * blockDim.x + threadIdx.x;
    int total = M << 7;
    int stride = gridDim.x * blockDim.x;
    for (; idx < total; idx += stride) {
        float v = A[idx];
        __nv_bfloat16 h = __float2bfloat16(v);
        float r = v - __bfloat162float(h);
        hi[idx] = h;
        lo[idx] = __float2bfloat16(r);
    }
}

__global__ void conv_wt_kernel(const float* __restrict__ W, int ldw,
                               int Kreal, int Nreal, int Kpad,
                               __nv_bfloat16* __restrict__ hi,
                               __nv_bfloat16* __restrict__ lo) {
    int idx = blockIdx.x * blockDim.x + threadIdx.x;
    int total = 256 * Kpad;
    if (idx >= total) return;
    int n = idx / Kpad, k = idx - n * Kpad;
    float v = (n < Nreal && k < Kreal) ? W[(size_t)k * ldw + n] : 0.f;
    __nv_bfloat16 h = __float2bfloat16(v);
    float r = v - __bfloat162float(h);
    hi[idx] = h;
    lo[idx] = __float2bfloat16(r);
}

// ---------------- mma / ldmatrix / cp.async helpers ------------------------
__device__ __forceinline__ void mma16816(float* c, const unsigned* a,
                                         unsigned b0, unsigned b1) {
    asm volatile(
        "mma.sync.aligned.m16n8k16.row.col.f32.bf16.bf16.f32 "
        "{%0,%1,%2,%3},{%4,%5,%6,%7},{%8,%9},{%0,%1,%2,%3};"
        : "+f"(c[0]), "+f"(c[1]), "+f"(c[2]), "+f"(c[3])
        : "r"(a[0]), "r"(a[1]), "r"(a[2]), "r"(a[3]), "r"(b0), "r"(b1));
}

__device__ __forceinline__ void ldsm_x4(unsigned* r, unsigned addr) {
    asm volatile("ldmatrix.sync.aligned.m8n8.x4.shared.b16 {%0,%1,%2,%3}, [%4];"
                 : "=r"(r[0]), "=r"(r[1]), "=r"(r[2]), "=r"(r[3]) : "r"(addr));
}

__device__ __forceinline__ void cpasync16(unsigned saddr, const void* gaddr, int bytes) {
    asm volatile("cp.async.cg.shared.global [%0], [%1], 16, %2;"
                 :: "r"(saddr), "l"(gaddr), "r"(bytes));
}

// ---------------- fused dual-B split-bf16 tensor-core GEMM -----------------
// (round-13 proven config: 256 thr, 128x128 tile, 2-stage, 2 blocks/SM)
#define SROW 40                       // bf16 per smem row (32 k + 8 pad)
#define ARR_BYTES (128 * SROW * 2)    // 10240
#define STAGE_BYTES (4 * ARR_BYTES)   // 40960  (Ah, Al, Bh, Bl)
#define GEMM_SMEM (2 * STAGE_BYTES)   // 81920

extern __shared__ __align__(16) unsigned char g_dynsmem[];

__global__ void __launch_bounds__(256, 2)
gemm_mma_dual_kernel(const __nv_bfloat16* __restrict__ Ahi,
                     const __nv_bfloat16* __restrict__ Alo, int Kpad,
                     const __nv_bfloat16* __restrict__ BT1h,
                     const __nv_bfloat16* __restrict__ BT1l,
                     const __nv_bfloat16* __restrict__ BT2h,
                     const __nv_bfloat16* __restrict__ BT2l,
                     const float* __restrict__ bias1,
                     const float* __restrict__ bias2,
                     float* __restrict__ C1, float* __restrict__ C2,
                     int ldc, int M, int Nreal) {
    unsigned smem_u32 = (unsigned)__cvta_generic_to_shared(g_dynsmem);
    int tid = threadIdx.x;
    int lane = tid & 31, wid = tid >> 5;
    int g = lane >> 2, tk = lane & 3;
    int wm = (wid & 3) * 32;       // warp row offset in tile
    int wn = (wid >> 2) * 64;      // warp col offset in tile
    int row0 = blockIdx.y * 128;
    int half = blockIdx.x >> 1;
    int col0 = (blockIdx.x & 1) * 128;

    const __nv_bfloat16* BTh = half ? BT2h : BT1h;
    const __nv_bfloat16* BTl = half ? BT2l : BT1l;
    const float* bias = half ? bias2 : bias1;
    float* C = half ? C2 : C1;

    float acc[2][8][4];
    #pragma unroll
    for (int i = 0; i < 2; i++)
        #pragma unroll
        for (int j = 0; j < 8; j++)
            #pragma unroll
            for (int q = 0; q < 4; q++) acc[i][j][q] = 0.f;

    int nk = Kpad >> 5;

    auto stage_tiles = [&](int buf, int k0) {
        unsigned sb = smem_u32 + buf * STAGE_BYTES;
        #pragma unroll
        for (int it = 0; it < 2; it++) {
            int f = tid + it * 256;
            int r = f >> 2, kg = f & 3;
            unsigned soff = (unsigned)(r * SROW + kg * 8) * 2;
            int arow = row0 + r;
            int ab = (arow < M) ? 16 : 0;
            int arc = (arow < M) ? arow : 0;
            size_t ka = (size_t)arc * Kpad + k0 + kg * 8;
            cpasync16(sb + soff,                 Ahi + ka, ab);
            cpasync16(sb + ARR_BYTES + soff,     Alo + ka, ab);
            size_t kb = (size_t)(col0 + r) * Kpad + k0 + kg * 8;
            cpasync16(sb + 2 * ARR_BYTES + soff, BTh + kb, 16);
            cpasync16(sb + 3 * ARR_BYTES + soff, BTl + kb, 16);
        }
    };

    stage_tiles(0, 0);
    asm volatile("cp.async.commit_group;");

    for (int i = 0; i < nk; i++) {
        if (i + 1 < nk) {
            stage_tiles((i + 1) & 1, (i + 1) * 32);
            asm volatile("cp.async.commit_group;");
            asm volatile("cp.async.wait_group 1;");
        } else {
            asm volatile("cp.async.wait_group 0;");
        }
        __syncthreads();

        unsigned sb = smem_u32 + (i & 1) * STAGE_BYTES;
        #pragma unroll
        for (int kk = 0; kk < 32; kk += 16) {
            unsigned ah[2][4], al[2][4];
            #pragma unroll
            for (int mf = 0; mf < 2; mf++) {
                int arow = wm + mf * 16 + (lane & 15);
                int acol = kk + ((lane >> 4) << 3);
                unsigned addr = sb + (unsigned)(arow * SROW + acol) * 2;
                ldsm_x4(ah[mf], addr);
                ldsm_x4(al[mf], addr + ARR_BYTES);
            }
            #pragma unroll
            for (int pr = 0; pr < 4; pr++) {
                unsigned bh[4], bl[4];
                int brow = wn + pr * 16 + (lane & 7) + ((lane >> 4) << 3);
                int bcol = kk + (((lane >> 3) & 1) << 3);
                unsigned addr = sb + 2 * ARR_BYTES + (unsigned)(brow * SROW + bcol) * 2;
                ldsm_x4(bh, addr);
                ldsm_x4(bl, addr + ARR_BYTES);
                #pragma unroll
                for (int sub = 0; sub < 2; sub++) {
                    int nf = pr * 2 + sub;
                    unsigned b0h = bh[sub * 2], b1h = bh[sub * 2 + 1];
                    unsigned b0l = bl[sub * 2], b1l = bl[sub * 2 + 1];
                    #pragma unroll
                    for (int mf = 0; mf < 2; mf++) {
                        mma16816(acc[mf][nf], ah[mf], b0h, b1h);  // hi*hi
                        mma16816(acc[mf][nf], al[mf], b0h, b1h);  // lo*hi
                        mma16816(acc[mf][nf], ah[mf], b0l, b1l);  // hi*lo
                    }
                }
            }
        }
        __syncthreads();
    }

    // epilogue: write ALL cols (acc == 0 for col >= Nreal; B zero-padded)
    // so downstream kernels may vector-load full 256-wide rows.
    #pragma unroll
    for (int mf = 0; mf < 2; mf++) {
        #pragma unroll
        for (int nf = 0; nf < 8; nf++) {
            int col = col0 + wn + nf * 8 + 2 * tk;
            float bv0 = (bias && col     < Nreal) ? bias[col]     : 0.f;
            float bv1 = (bias && col + 1 < Nreal) ? bias[col + 1] : 0.f;
            int r = row0 + wm + mf * 16 + g;
            if (r < M) {
                float2 v = make_float2(acc[mf][nf][0] + bv0, acc[mf][nf][1] + bv1);
                *(float2*)&C[(size_t)r * ldc + col] = v;
            }
            int r2 = r + 8;
            if (r2 < M) {
                float2 v = make_float2(acc[mf][nf][2] + bv0, acc[mf][nf][3] + bv1);
                *(float2*)&C[(size_t)r2 * ldc + col] = v;
            }
        }
    }
}

// ---------------- fused GATv2 softmax-aggregate (float4 gathers) -----------
// one warp per dst node; lane owns 8 contiguous dims (2x LDG.128 per row);
// xl/xr rows fully defined (padding cols written as zero by GEMM epilogue).
__global__ void gat_agg_kernel(const float* __restrict__ xl,
                               const float* __restrict__ xr,
                               const float* __restrict__ att,
                               const int* __restrict__ rowptr,
                               const int* __restrict__ colsrc,
                               __nv_bfloat16* __restrict__ ohi,
                               __nv_bfloat16* __restrict__ olo,
                               int n, int do_relu) {
    int w = (blockIdx.x * blockDim.x + threadIdx.x) >> 5;
    if (w >= n) return;
    int lane = threadIdx.x & 31;
    int d0 = lane * 8;

    float attv[8], xrv[8], acc[8];
    {
        const float4* xr4 = (const float4*)(xr + (size_t)w * DPAD + d0);
        float4 x0 = xr4[0], x1 = xr4[1];
        xrv[0]=x0.x; xrv[1]=x0.y; xrv[2]=x0.z; xrv[3]=x0.w;
        xrv[4]=x1.x; xrv[5]=x1.y; xrv[6]=x1.z; xrv[7]=x1.w;
        #pragma unroll
        for (int j = 0; j < 8; j++) {
            int d = d0 + j;
            attv[j] = (d < DDIM) ? att[d] : 0.f;   // att input is len-250
            acc[j] = 0.f;
        }
    }
    float m = -FLT_MAX, s = 0.f;
    int beg = rowptr[w], end = rowptr[w + 1];
    for (int p = beg; p < end; p++) {
        int src = colsrc[p];
        const float4* xs4 = (const float4*)(xl + (size_t)src * DPAD + d0);
        float4 v0 = xs4[0], v1 = xs4[1];
        float xv[8] = { v0.x, v0.y, v0.z, v0.w, v1.x, v1.y, v1.z, v1.w };
        float part = 0.f;
        #pragma unroll
        for (int j = 0; j < 8; j++) {
            float hsum = xv[j] + xrv[j];
            float lr = hsum > 0.f ? hsum : 0.2f * hsum;
            part += attv[j] * lr;
        }
        #pragma unroll
        for (int off = 16; off; off >>= 1)
            part += __shfl_xor_sync(0xffffffffu, part, off);
        float mn = fmaxf(m, part);
        float c   = __expf(m - mn);
        float wgt = __expf(part - mn);
        s = s * c + wgt;
        #pragma unroll
        for (int j = 0; j < 8; j++) acc[j] = acc[j] * c + wgt * xv[j];
        m = mn;
    }
    float inv = 1.f / s;
    __nv_bfloat16 hb[8], lb[8];
    #pragma unroll
    for (int j = 0; j < 8; j++) {
        float v = acc[j] * inv;
        if (do_relu) v = fmaxf(v, 0.f);
        if (d0 + j >= DDIM) v = 0.f;
        hb[j] = __float2bfloat16(v);
        lb[j] = __float2bfloat16(v - __bfloat162float(hb[j]));
    }
    size_t o = (size_t)w * DPAD + d0;
    *(uint4*)(ohi + o) = *(uint4*)hb;
    *(uint4*)(olo + o) = *(uint4*)lb;
}

// ---------------- head: out[q] = relu(dot(relu(A[q0]+B[q1]), Wm2)+bm2) -----
__global__ void head_kernel(const int* __restrict__ query,
                            const float* __restrict__ Atab,
                            const float* __restrict__ Btab,
                            const float* __restrict__ Wm2,
                            const float* __restrict__ bm2,
                            float* __restrict__ out, int Q) {
    int q = (blockIdx.x * blockDim.x + threadIdx.x) >> 5;
    if (q >= Q) return;
    int lane = threadIdx.x & 31;
    int j0 = lane * 8;
    int q0 = query[2 * q], q1 = query[2 * q + 1];
    const float4* a4 = (const float4*)(Atab + (size_t)q0 * HDIM + j0);
    const float4* b4 = (const float4*)(Btab + (size_t)q1 * HDIM + j0);
    const float4* w4 = (const float4*)(Wm2 + j0);
    float partial = 0.f;
    #pragma unroll
    for (int h = 0; h < 2; h++) {
        float4 a = a4[h], b = b4[h], w = w4[h];
        partial += fmaxf(a.x + b.x, 0.f) * w.x;
        partial += fmaxf(a.y + b.y, 0.f) * w.y;
        partial += fmaxf(a.z + b.z, 0.f) * w.z;
        partial += fmaxf(a.w + b.w, 0.f) * w.w;
    }
    #pragma unroll
    for (int off = 16; off; off >>= 1)
        partial += __shfl_down_sync(0xffffffffu, partial, off);
    if (lane == 0) out[q] = fmaxf(partial + bm2[0], 0.f);
}

// ---------------------------------------------------------------------------
extern "C" void kernel_launch(void* const* d_in, const int* in_sizes, int n_in,
                              void* d_out, int out_size) {
    const float* x    = (const float*)d_in[0];
    const int*   ei   = (const int*)  d_in[1];
    const int*   qry  = (const int*)  d_in[2];
    const float* W1l  = (const float*)d_in[3];
    const float* b1l  = (const float*)d_in[4];
    const float* W1r  = (const float*)d_in[5];
    const float* b1r  = (const float*)d_in[6];
    const float* att1 = (const float*)d_in[7];
    const float* W2l  = (const float*)d_in[8];
    const float* b2l  = (const float*)d_in[9];
    const float* W2r  = (const float*)d_in[10];
    const float* b2r  = (const float*)d_in[11];
    const float* att2 = (const float*)d_in[12];
    const float* Wm1  = (const float*)d_in[13];
    const float* bm1  = (const float*)d_in[14];
    const float* Wm2  = (const float*)d_in[15];
    const float* bm2  = (const float*)d_in[16];
    float* out = (float*)d_out;

    const int N = in_sizes[0] / FIN;        // 50000
    const int E = in_sizes[1] / 2;          // 800000
    const int Q = in_sizes[2] / 2;          // 200000
    const int Etot = E + N;

    float *p_xl, *p_xr;
    int *p_deg, *p_cursor, *p_rowptr, *p_colsrc;
    __nv_bfloat16 *p_ahi, *p_alo, *p_bthi, *p_btlo;
    cudaGetSymbolAddress((void**)&p_xl,     g_xl);
    cudaGetSymbolAddress((void**)&p_xr,     g_xr);
    cudaGetSymbolAddress((void**)&p_deg,    g_deg);
    cudaGetSymbolAddress((void**)&p_cursor, g_cursor);
    cudaGetSymbolAddress((void**)&p_rowptr, g_rowptr);
    cudaGetSymbolAddress((void**)&p_colsrc, g_colsrc);
    cudaGetSymbolAddress((void**)&p_ahi,    g_ahi);
    cudaGetSymbolAddress((void**)&p_alo,    g_alo);
    cudaGetSymbolAddress((void**)&p_bthi,   g_bthi);
    cudaGetSymbolAddress((void**)&p_btlo,   g_btlo);
    __nv_bfloat16* bthi[6], *btlo[6];
    for (int i = 0; i < 6; i++) {
        bthi[i] = p_bthi + i * 256 * 256;
        btlo[i] = p_btlo + i * 256 * 256;
    }

    cudaFuncSetAttribute(gemm_mma_dual_kernel,
                         cudaFuncAttributeMaxDynamicSharedMemorySize, GEMM_SMEM);

    const int TPB = 256;
    int agg_blocks = (N * 32 + TPB - 1) / TPB;
    int wt_blocks = (256 * 256 + TPB - 1) / TPB;
    dim3 ggrid(4, (N + 127) / 128);   // 2 col-tiles x 2 weight halves

    // ---- fork a non-blocking side stream for independent work -------------
    cudaStream_t s2;
    cudaStreamCreateWithFlags(&s2, cudaStreamNonBlocking);
    cudaEvent_t ev0, ev1;
    cudaEventCreateWithFlags(&ev0, cudaEventDisableTiming);
    cudaEventCreateWithFlags(&ev1, cudaEventDisableTiming);
    cudaEventRecord(ev0, 0);

    // ---------- main: layer-1 convert + fused dual GEMM (launch #4) --------
    conv_act_kernel<<<2048, TPB>>>(x, N, p_ahi, p_alo);
    conv_wt_kernel<<<wt_blocks, TPB>>>(W1l, DDIM, FIN, DDIM, FIN, bthi[0], btlo[0]);
    conv_wt_kernel<<<wt_blocks, TPB>>>(W1r, DDIM, FIN, DDIM, FIN, bthi[1], btlo[1]);
    gemm_mma_dual_kernel<<<ggrid, 256, GEMM_SMEM>>>(p_ahi, p_alo, FIN,
        bthi[0], btlo[0], bthi[1], btlo[1], b1l, b1r, p_xl, p_xr, DPAD, N, DDIM);

    // ---------- side: CSR build + layer-2/head weight conversion -----------
    cudaStreamWaitEvent(s2, ev0, 0);
    zero_deg_kernel<<<(N + TPB - 1) / TPB, TPB, 0, s2>>>(p_deg, N);
    hist_kernel<<<(Etot + TPB - 1) / TPB, TPB, 0, s2>>>(ei, p_deg, E, Etot);
    scan_kernel<<<1, 1024, 0, s2>>>(p_deg, p_rowptr, p_cursor, N);
    scatter_kernel<<<(Etot + TPB - 1) / TPB, TPB, 0, s2>>>(ei, p_cursor, p_colsrc, E, Etot);
    conv_wt_kernel<<<wt_blocks, TPB, 0, s2>>>(W2l, DDIM, DDIM, DDIM, DPAD, bthi[2], btlo[2]);
    conv_wt_kernel<<<wt_blocks, TPB, 0, s2>>>(W2r, DDIM, DDIM, DDIM, DPAD, bthi[3], btlo[3]);
    conv_wt_kernel<<<wt_blocks, TPB, 0, s2>>>(Wm1,               HDIM, DDIM, HDIM, DPAD, bthi[4], btlo[4]);
    conv_wt_kernel<<<wt_blocks, TPB, 0, s2>>>(Wm1 + DDIM * HDIM, HDIM, DDIM, HDIM, DPAD, bthi[5], btlo[5]);
    cudaEventRecord(ev1, s2);

    // ---------- join, then the dependent chain -----------------------------
    cudaStreamWaitEvent(0, ev1, 0);

    gat_agg_kernel<<<agg_blocks, TPB>>>(p_xl, p_xr, att1, p_rowptr, p_colsrc,
                                        p_ahi, p_alo, N, 1);

    gemm_mma_dual_kernel<<<ggrid, 256, GEMM_SMEM>>>(p_ahi, p_alo, DPAD,
        bthi[2], btlo[2], bthi[3], btlo[3], b2l, b2r, p_xl, p_xr, DPAD, N, DDIM);

    gat_agg_kernel<<<agg_blocks, TPB>>>(p_xl, p_xr, att2, p_rowptr, p_colsrc,
                                        p_ahi, p_alo, N, 0);

    gemm_mma_dual_kernel<<<ggrid, 256, GEMM_SMEM>>>(p_ahi, p_alo, DPAD,
        bthi[4], btlo[4], bthi[5], btlo[5], bm1, nullptr, p_xl, p_xr, HDIM, N, HDIM);

    int q_blocks = (Q * 32 + TPB - 1) / TPB;
    head_kernel<<<q_blocks, TPB>>>(qry, p_xl, p_xr, Wm2, bm2, out, Q);

    cudaEventDestroy(ev0);
    cudaEventDestroy(ev1);
    cudaStreamDestroy(s2);
}